// round 13
// baseline (speedup 1.0000x reference)
#include <cuda_runtime.h>
#include <cuda_bf16.h>
#include <cuda_fp16.h>
#include <math.h>
#include <stdint.h>

// Problem dims
#define B_  512
#define H_  1024
#define L_  256
#define V_  10000
#define H2_ 2048
#define H3_ 3072

// ---------------- scratch (device globals; no allocation) ----------------
__device__ float g_comb[B_ * H2_];
__device__ float g_attn_applied[B_ * H_];
__device__ float g_x[B_ * H_];
__device__ float g_gi[B_ * H3_];
__device__ float g_gh[B_ * H3_];
__device__ float g_part[8 * B_ * L_];   // split-K partials (4MB; holds 2*B*H too)

// ---------------- helpers ----------------
#define PACK_F32X2(d, lo, hi) \
    asm("mov.b64 %0, {%1, %2};" : "=l"(d) : "f"(lo), "f"(hi))
#define UNPACK_F32X2(lo, hi, v) \
    asm("mov.b64 {%0, %1}, %2;" : "=f"(lo), "=f"(hi) : "l"(v))
#define FMA_F32X2(d, a, b, c) \
    asm("fma.rn.f32x2 %0, %1, %2, %3;" : "=l"(d) : "l"(a), "l"(b), "l"(c))

__device__ __forceinline__ uint32_t packh2(float lo, float hi) {
    __half2 h = __floats2half2_rn(lo, hi);   // .x = lo (low 16 bits)
    return *reinterpret_cast<uint32_t*>(&h);
}

// ---------------- fused gather+concat ----------------
__global__ void concat_emb_kernel(const int* __restrict__ ids,
                                  const float* __restrict__ emb,
                                  const float* __restrict__ other) {
    int i = blockIdx.x * blockDim.x + threadIdx.x;
    int b = i >> 11;
    int j = i & (H2_ - 1);
    g_comb[i] = (j < H_) ? emb[(size_t)ids[b] * H_ + j]
                         : other[(size_t)b * H_ + (j - H_)];
}

// ==================== pipelined fp16 mma GEMM core (fp32 accum) ====================
// C = A(M,K) @ W(K,N) (+bias). 256 thr = 8 warps (4m x 2n), BM=128 BN=64 BK=32.
// m16n8k16.f16; smem packed half2 (2 k-elems per u32).
// As [2][128][20] u32, Ws [2][16][72] u32 — conflict-free fragment walks.
struct GemmArgs {
    const float* A;
    const float* W;
    const float* bias;
    float* C;
};

template <bool ADDBIAS>
__device__ __forceinline__ void gemm_core(const float* __restrict__ A,
                                          const float* __restrict__ W,
                                          const float* __restrict__ bias,
                                          float* __restrict__ C,
                                          int N, int K, int kbeg, int kT,
                                          int bm, int bn) {
    __shared__ uint32_t As[2][128][20];   // 20480 B
    __shared__ uint32_t Ws[2][16][72];    //  9216 B

    const int tid = threadIdx.x;
    const int lane = tid & 31;
    const int wid = tid >> 5;
    const int gid = lane >> 2;
    const int tig = lane & 3;
    const int warp_m = (wid & 3) * 32;
    const int warp_n = (wid >> 2) * 32;

    // A staging: rows sa_r (+32r), k cols sa_c..sa_c+3 -> 2 u32 pairs
    const int sa_r = tid >> 3;           // 0..31
    const int sa_c = (tid & 7) * 4;      // 0..28
    const int sa_p = sa_c >> 1;          // pair col 0..14
    // W staging: k-pair row pk (covers k=2pk,2pk+1), n cols wc..wc+3
    const int pk = tid >> 4;             // 0..15
    const int wc = (tid & 15) * 4;       // 0..60
    const int gnw = bn + wc;
    const bool wok = (gnw < N);

    const float* Ap = A + (size_t)(bm + sa_r) * K + kbeg + sa_c;
    const float* Wp0 = W + (size_t)(kbeg + 2 * pk) * N + gnw;
    const float* Wp1 = W + (size_t)(kbeg + 2 * pk + 1) * N + gnw;

    float acc[2][4][4];
#pragma unroll
    for (int mi = 0; mi < 2; mi++)
#pragma unroll
        for (int ni = 0; ni < 4; ni++)
#pragma unroll
            for (int r = 0; r < 4; r++) acc[mi][ni][r] = 0.f;

    float4 av[4];
    float4 wv0, wv1;

    auto LDG = [&](int t) {
        const float* ap = Ap + t * 32;
#pragma unroll
        for (int r = 0; r < 4; r++)
            av[r] = *reinterpret_cast<const float4*>(ap + (size_t)(32 * r) * K);
        if (wok) {
            wv0 = *reinterpret_cast<const float4*>(Wp0 + (size_t)(t * 32) * N);
            wv1 = *reinterpret_cast<const float4*>(Wp1 + (size_t)(t * 32) * N);
        } else {
            wv0 = make_float4(0.f, 0.f, 0.f, 0.f);
            wv1 = wv0;
        }
    };

    auto STS = [&](int p) {
#pragma unroll
        for (int r = 0; r < 4; r++) {
            int m = sa_r + 32 * r;
            uint2 t2;
            t2.x = packh2(av[r].x, av[r].y);
            t2.y = packh2(av[r].z, av[r].w);
            *reinterpret_cast<uint2*>(&As[p][m][sa_p]) = t2;
        }
        uint4 t4;
        t4.x = packh2(wv0.x, wv1.x);
        t4.y = packh2(wv0.y, wv1.y);
        t4.z = packh2(wv0.z, wv1.z);
        t4.w = packh2(wv0.w, wv1.w);
        *reinterpret_cast<uint4*>(&Ws[p][pk][wc]) = t4;
    };

    LDG(0);
    STS(0);
    __syncthreads();

    int p = 0;
    for (int t = 0; t < kT; t++) {
        if (t + 1 < kT) LDG(t + 1);

#pragma unroll
        for (int ks = 0; ks < 2; ks++) {       // two k=16 steps per 32-k tile
            const int kp = ks * 8;             // k-pair offset
            uint32_t af[2][4];
#pragma unroll
            for (int mi = 0; mi < 2; mi++) {
                int ar = warp_m + mi * 16 + gid;
                af[mi][0] = As[p][ar][kp + tig];
                af[mi][1] = As[p][ar + 8][kp + tig];
                af[mi][2] = As[p][ar][kp + tig + 4];
                af[mi][3] = As[p][ar + 8][kp + tig + 4];
            }
            uint32_t bf[4][2];
#pragma unroll
            for (int ni = 0; ni < 4; ni++) {
                int bc = warp_n + ni * 8 + gid;
                bf[ni][0] = Ws[p][kp + tig][bc];
                bf[ni][1] = Ws[p][kp + tig + 4][bc];
            }
#pragma unroll
            for (int mi = 0; mi < 2; mi++)
#pragma unroll
                for (int ni = 0; ni < 4; ni++) {
                    asm volatile(
                        "mma.sync.aligned.m16n8k16.row.col.f32.f16.f16.f32 "
                        "{%0,%1,%2,%3}, {%4,%5,%6,%7}, {%8,%9}, {%0,%1,%2,%3};\n"
                        : "+f"(acc[mi][ni][0]), "+f"(acc[mi][ni][1]),
                          "+f"(acc[mi][ni][2]), "+f"(acc[mi][ni][3])
                        : "r"(af[mi][0]), "r"(af[mi][1]),
                          "r"(af[mi][2]), "r"(af[mi][3]),
                          "r"(bf[ni][0]), "r"(bf[ni][1]));
                }
        }

        if (t + 1 < kT) STS(p ^ 1);
        __syncthreads();
        p ^= 1;
    }

    // epilogue
#pragma unroll
    for (int mi = 0; mi < 2; mi++) {
        int r0 = bm + warp_m + mi * 16 + gid;
#pragma unroll
        for (int ni = 0; ni < 4; ni++) {
            int c0 = bn + warp_n + ni * 8 + 2 * tig;
            if (c0 < N) {
                float v0 = acc[mi][ni][0], v1 = acc[mi][ni][1];
                float v2 = acc[mi][ni][2], v3 = acc[mi][ni][3];
                if (ADDBIAS) {
                    float bz0 = bias[c0];
                    float bz1 = (c0 + 1 < N) ? bias[c0 + 1] : 0.f;
                    v0 += bz0; v1 += bz1; v2 += bz0; v3 += bz1;
                }
                C[(size_t)r0 * N + c0] = v0;
                C[(size_t)(r0 + 8) * N + c0] = v2;
                if (c0 + 1 < N) {
                    C[(size_t)r0 * N + c0 + 1] = v1;
                    C[(size_t)(r0 + 8) * N + c0 + 1] = v3;
                }
            }
        }
    }
}

// MODE: 0 = plain (full K, bias), 1 = split-K (z = k-chunk, raw partials)
template <int MODE>
__global__ void __launch_bounds__(256)
gemm_h16p(GemmArgs g0, int M, int N, int K, int kLen) {
    const int kbeg = (MODE == 1) ? blockIdx.z * kLen : 0;
    const int kT = ((MODE == 1) ? kLen : K) / 32;
    float* C = g0.C + ((MODE == 1) ? (size_t)blockIdx.z * M * N : 0);
    const int bm = blockIdx.y * 128;
    const int bn = blockIdx.x * 64;
    if (MODE == 1)
        gemm_core<false>(g0.A, g0.W, nullptr, C, N, K, kbeg, kT, bm, bn);
    else
        gemm_core<true>(g0.A, g0.W, g0.bias, C, N, K, kbeg, kT, bm, bn);
}

// ==================== fused: gh GEMM (192 blocks) + attn_apply (2048) ====================
// gh = hidden @ w_hh + b_hh runs inside attn_apply's DRAM-bound window.
#define GH_NT (H3_ / 64)            // 48 n-tiles
#define GH_BLOCKS (GH_NT * (B_ / 128))   // 192

__global__ void __launch_bounds__(256)
fused_gh_attn_kernel(const float* __restrict__ hidden,
                     const float* __restrict__ w_hh,
                     const float* __restrict__ b_hh,
                     const float* __restrict__ attw,
                     const float* __restrict__ enc) {
    if (blockIdx.x < GH_BLOCKS) {
        const int bn = (blockIdx.x % GH_NT) * 64;
        const int bm = (blockIdx.x / GH_NT) * 128;
        gemm_core<true>(hidden, w_hh, b_hh, g_gh, H3_, H_, 0, H_ / 32, bm, bn);
        return;
    }
    // attn_apply
    int idx = blockIdx.x - GH_BLOCKS;      // 0..2047
    int b = idx >> 2;
    int hc = idx & 3;
    int t = threadIdx.x;
    __shared__ float w[L_];
    w[t] = attw[b * L_ + t];
    __syncthreads();
    int h = hc * 256 + t;
    const float* e = enc + (size_t)b * L_ * H_ + h;
    float acc = 0.f;
#pragma unroll 8
    for (int l = 0; l < L_; l++)
        acc += w[l] * e[(size_t)l * H_];
    g_attn_applied[(size_t)b * H_ + h] = acc;
}

// ---------------- exact-fp32 FFMA2 GEMM (attn logits only) ----------------
__global__ void gemm_f32x2_split_kernel(const float* __restrict__ A,
                                        const float* __restrict__ W,
                                        float* __restrict__ C,
                                        int M, int N, int K, int kLen) {
    __shared__ float As[16][128];
    __shared__ float Ws[16][68];

    const int tid = threadIdx.x;
    const int bm = blockIdx.y * 128;
    const int bn = blockIdx.x * 64;
    const int tm = (tid >> 4) * 8;
    const int tn = (tid & 15) * 4;

    const int am = tid >> 1;
    const int ak = (tid & 1) * 8;
    const float* Ap = A + (size_t)(bm + am) * K + ak;
    const int wk = tid >> 4;
    const int wn = (tid & 15) * 4;
    const int gnw = bn + wn;
    const float* Wp = W + (size_t)wk * N + gnw;

    unsigned long long acc[4][4];
#pragma unroll
    for (int i = 0; i < 4; i++)
#pragma unroll
        for (int j = 0; j < 4; j++) acc[i][j] = 0ULL;

    const int kbeg = blockIdx.z * kLen;
    const int kend = kbeg + kLen;

    for (int k0 = kbeg; k0 < kend; k0 += 16) {
        float4 av0 = *reinterpret_cast<const float4*>(Ap + k0);
        float4 av1 = *reinterpret_cast<const float4*>(Ap + k0 + 4);
        float4 wv = make_float4(0.f, 0.f, 0.f, 0.f);
        if (gnw < N)
            wv = *reinterpret_cast<const float4*>(Wp + (size_t)k0 * N);

        __syncthreads();
        As[ak + 0][am] = av0.x; As[ak + 1][am] = av0.y;
        As[ak + 2][am] = av0.z; As[ak + 3][am] = av0.w;
        As[ak + 4][am] = av1.x; As[ak + 5][am] = av1.y;
        As[ak + 6][am] = av1.z; As[ak + 7][am] = av1.w;
        *reinterpret_cast<float4*>(&Ws[wk][wn]) = wv;
        __syncthreads();

#pragma unroll
        for (int k = 0; k < 16; k++) {
            float4 a0 = *reinterpret_cast<const float4*>(&As[k][tm]);
            float4 a1 = *reinterpret_cast<const float4*>(&As[k][tm + 4]);
            float4 w  = *reinterpret_cast<const float4*>(&Ws[k][tn]);
            unsigned long long ap[4], wb[4];
            PACK_F32X2(ap[0], a0.x, a0.y);
            PACK_F32X2(ap[1], a0.z, a0.w);
            PACK_F32X2(ap[2], a1.x, a1.y);
            PACK_F32X2(ap[3], a1.z, a1.w);
            PACK_F32X2(wb[0], w.x, w.x);
            PACK_F32X2(wb[1], w.y, w.y);
            PACK_F32X2(wb[2], w.z, w.z);
            PACK_F32X2(wb[3], w.w, w.w);
#pragma unroll
            for (int i = 0; i < 4; i++)
#pragma unroll
                for (int j = 0; j < 4; j++)
                    FMA_F32X2(acc[i][j], ap[i], wb[j], acc[i][j]);
        }
    }

    float* Cb = C + (size_t)blockIdx.z * M * N;
#pragma unroll
    for (int i = 0; i < 4; i++) {
        int r0 = bm + tm + 2 * i;
#pragma unroll
        for (int j = 0; j < 4; j++) {
            int c = bn + tn + j;
            if (c < N) {
                float lo, hi;
                UNPACK_F32X2(lo, hi, acc[i][j]);
                Cb[(size_t)r0 * N + c] = lo;
                Cb[(size_t)(r0 + 1) * N + c] = hi;
            }
        }
    }
}

// ---------------- softmax (attn) ----------------
__global__ void softmax_attn_kernel(const float* __restrict__ attn_b,
                                    float* __restrict__ out) {
    int b = blockIdx.x;
    int t = threadIdx.x;
    float v = attn_b[t];
#pragma unroll
    for (int s = 0; s < 8; s++)
        v += g_part[(size_t)s * B_ * L_ + b * L_ + t];
    __shared__ float red[256];
    red[t] = v;
    __syncthreads();
    for (int s = 128; s; s >>= 1) {
        if (t < s) red[t] = fmaxf(red[t], red[t + s]);
        __syncthreads();
    }
    float m = red[0];
    __syncthreads();
    float e = expf(v - m);
    red[t] = e;
    __syncthreads();
    for (int s = 128; s; s >>= 1) {
        if (t < s) red[t] += red[t + s];
        __syncthreads();
    }
    out[b * L_ + t] = e / red[0];
}

// ---------------- reduce 2 K-partials + bias + relu -> g_x ----------------
__global__ void reduce_relu_kernel(const float* __restrict__ bias) {
    int i = blockIdx.x * blockDim.x + threadIdx.x;
    int j = i & (H_ - 1);
    float v = g_part[i] + g_part[B_ * H_ + i] + bias[j];
    g_x[i] = fmaxf(v, 0.f);
}

// ---------------- GRU elementwise ----------------
__global__ void gru_kernel(const float* __restrict__ h,
                           float* __restrict__ new_h) {
    int i = blockIdx.x * blockDim.x + threadIdx.x;
    int b = i >> 10;
    int j = i & (H_ - 1);
    const float* gib = g_gi + (size_t)b * H3_;
    const float* ghb = g_gh + (size_t)b * H3_;
    float r = 1.f / (1.f + expf(-(gib[j] + ghb[j])));
    float z = 1.f / (1.f + expf(-(gib[H_ + j] + ghb[H_ + j])));
    float n = tanhf(gib[2 * H_ + j] + r * ghb[2 * H_ + j]);
    new_h[i] = (1.f - z) * n + z * h[i];
}

// ---------------- log_softmax (online max+sum, 2 passes total) ----------------
__global__ void logsoftmax_kernel(float* __restrict__ x) {
    int b = blockIdx.x;
    int t = threadIdx.x;
    float* row = x + (size_t)b * V_;
    __shared__ float redm[256];
    __shared__ float reds[256];
    float m = -1e30f, s = 0.f;
    for (int i = t; i < V_; i += 256) {
        float v = row[i];
        float mn = fmaxf(m, v);
        s = s * expf(m - mn) + expf(v - mn);
        m = mn;
    }
    redm[t] = m;
    reds[t] = s;
    __syncthreads();
    for (int st = 128; st; st >>= 1) {
        if (t < st) {
            float m2 = redm[t + st], s2 = reds[t + st];
            float mn = fmaxf(redm[t], m2);
            reds[t] = reds[t] * expf(redm[t] - mn) + s2 * expf(m2 - mn);
            redm[t] = mn;
        }
        __syncthreads();
    }
    float lse = redm[0] + logf(reds[0]);
    for (int i = t; i < V_; i += 256) row[i] -= lse;
}

// ---------------- launch ----------------
extern "C" void kernel_launch(void* const* d_in, const int* in_sizes, int n_in,
                              void* d_out, int out_size) {
    const int*   input_ids = (const int*)d_in[0];
    const float* hidden    = (const float*)d_in[1];
    const float* enc       = (const float*)d_in[2];
    const float* emb       = (const float*)d_in[3];
    const float* attn_w    = (const float*)d_in[4];
    const float* attn_b    = (const float*)d_in[5];
    const float* comb_w    = (const float*)d_in[6];
    const float* comb_b    = (const float*)d_in[7];
    const float* w_ih      = (const float*)d_in[8];
    const float* w_hh      = (const float*)d_in[9];
    const float* b_ih      = (const float*)d_in[10];
    const float* b_hh      = (const float*)d_in[11];
    const float* out_w     = (const float*)d_in[12];
    const float* out_b     = (const float*)d_in[13];

    float* out       = (float*)d_out;
    float* new_h_out = out + (size_t)B_ * V_;
    float* attw_out  = new_h_out + (size_t)B_ * H_;

    float *p_comb, *p_app, *p_x, *p_gi, *p_part;
    cudaGetSymbolAddress((void**)&p_comb, g_comb);
    cudaGetSymbolAddress((void**)&p_app,  g_attn_applied);
    cudaGetSymbolAddress((void**)&p_x,    g_x);
    cudaGetSymbolAddress((void**)&p_gi,   g_gi);
    cudaGetSymbolAddress((void**)&p_part, g_part);

    // 1. g_comb = [emb[ids] | hidden]
    concat_emb_kernel<<<(B_ * H2_) / 256, 256>>>(input_ids, emb, hidden);
    // 2. attn logits, exact fp32, split-K=8 -> partials
    {
        dim3 g(L_ / 64, B_ / 128, 8);
        gemm_f32x2_split_kernel<<<g, 256>>>(p_comb, attn_w, p_part,
                                            B_, L_, H2_, H2_ / 8);
    }
    // 3. reduce + softmax -> attw_out
    softmax_attn_kernel<<<B_, 256>>>(attn_b, attw_out);
    // 4. fused: gh GEMM (overlapped) + attn_applied
    fused_gh_attn_kernel<<<GH_BLOCKS + (B_ * (H_ / 256)), 256>>>(
        hidden, w_hh, b_hh, attw_out, enc);
    // 5. g_comb = [emb[ids] | attn_applied]
    concat_emb_kernel<<<(B_ * H2_) / 256, 256>>>(input_ids, emb, p_app);
    // 6. comb GEMM (fp16 mma), split-K=2 -> partials
    {
        dim3 g(H_ / 64, B_ / 128, 2);
        GemmArgs a0 = {p_comb, comb_w, nullptr, p_part};
        gemm_h16p<1><<<g, 256>>>(a0, B_, H_, H2_, H2_ / 2);
    }
    // 7. x = relu(p0 + p1 + bias)
    reduce_relu_kernel<<<(B_ * H_) / 256, 256>>>(comb_b);
    // 8. gi = x @ w_ih + b_ih
    {
        dim3 g(H3_ / 64, B_ / 128, 1);
        GemmArgs a0 = {p_x, w_ih, b_ih, p_gi};
        gemm_h16p<0><<<g, 256>>>(a0, B_, H3_, H_, H_);
    }
    // 9. GRU -> new_hidden
    gru_kernel<<<(B_ * H_) / 256, 256>>>(hidden, new_h_out);
    // 10. out-proj (fp16 mma)
    {
        dim3 g((V_ + 63) / 64, B_ / 128, 1);
        GemmArgs a0 = {new_h_out, out_w, out_b, out};
        gemm_h16p<0><<<g, 256>>>(a0, B_, V_, H_, H_);
    }
    // 11. log_softmax (online)
    logsoftmax_kernel<<<B_, 256>>>(out);
}

// round 14
// speedup vs baseline: 1.2464x; 1.2464x over previous
#include <cuda_runtime.h>
#include <cuda_bf16.h>
#include <cuda_fp16.h>
#include <math.h>
#include <stdint.h>

// Problem dims
#define B_  512
#define H_  1024
#define L_  256
#define V_  10000
#define H2_ 2048
#define H3_ 3072

// ---------------- scratch (device globals; no allocation) ----------------
__device__ float g_comb[B_ * H2_];
__device__ float g_x[B_ * H_];
__device__ float g_gi[B_ * H3_];
__device__ float g_gh[B_ * H3_];
__device__ float g_part[8 * B_ * L_];   // split-K partials (4MB; holds 2*B*H too)

// ---------------- helpers ----------------
#define PACK_F32X2(d, lo, hi) \
    asm("mov.b64 %0, {%1, %2};" : "=l"(d) : "f"(lo), "f"(hi))
#define UNPACK_F32X2(lo, hi, v) \
    asm("mov.b64 {%0, %1}, %2;" : "=f"(lo), "=f"(hi) : "l"(v))
#define FMA_F32X2(d, a, b, c) \
    asm("fma.rn.f32x2 %0, %1, %2, %3;" : "=l"(d) : "l"(a), "l"(b), "l"(c))

__device__ __forceinline__ uint32_t packh2(float lo, float hi) {
    __half2 h = __floats2half2_rn(lo, hi);   // .x = lo (low 16 bits)
    return *reinterpret_cast<uint32_t*>(&h);
}

// ---------------- fused gather+concat: g_comb = [emb[ids] | other] ----------------
__global__ void concat_emb_kernel(const int* __restrict__ ids,
                                  const float* __restrict__ emb,
                                  const float* __restrict__ other) {
    int i = blockIdx.x * blockDim.x + threadIdx.x;
    int b = i >> 11;
    int j = i & (H2_ - 1);
    g_comb[i] = (j < H_) ? emb[(size_t)ids[b] * H_ + j]
                         : other[(size_t)b * H_ + (j - H_)];
}

// ==================== pipelined fp16 mma GEMM (fp32 accum) ====================
// C = A(M,K) @ W(K,N) (+bias). 256 thr = 8 warps (4m x 2n), BM=128 BN=64 BK=32.
// m16n8k16.f16; smem packed half2 (2 k-elems per u32).
// As [2][128][20] u32, Ws [2][16][72] u32 — conflict-free fragment walks.
struct GemmArgs {
    const float* A;
    const float* W;
    const float* bias;
    float* C;
};

template <bool ADDBIAS>
__device__ __forceinline__ void gemm_core(const float* __restrict__ A,
                                          const float* __restrict__ W,
                                          const float* __restrict__ bias,
                                          float* __restrict__ C,
                                          int N, int K, int kbeg, int kT) {
    __shared__ uint32_t As[2][128][20];   // 20480 B
    __shared__ uint32_t Ws[2][16][72];    //  9216 B  (29696 total, static)

    const int tid = threadIdx.x;
    const int lane = tid & 31;
    const int wid = tid >> 5;
    const int gid = lane >> 2;
    const int tig = lane & 3;
    const int warp_m = (wid & 3) * 32;
    const int warp_n = (wid >> 2) * 32;

    const int bm = blockIdx.y * 128;
    const int bn = blockIdx.x * 64;

    // A staging: rows sa_r (+32r), k cols sa_c..sa_c+3 -> 2 u32 pairs
    const int sa_r = tid >> 3;           // 0..31
    const int sa_c = (tid & 7) * 4;      // 0..28
    const int sa_p = sa_c >> 1;          // pair col 0..14
    // W staging: k-pair row pk (covers k=2pk,2pk+1), n cols wc..wc+3
    const int pk = tid >> 4;             // 0..15
    const int wc = (tid & 15) * 4;       // 0..60
    const int gnw = bn + wc;
    const bool wok = (gnw < N);

    const float* Ap = A + (size_t)(bm + sa_r) * K + kbeg + sa_c;
    const float* Wp0 = W + (size_t)(kbeg + 2 * pk) * N + gnw;
    const float* Wp1 = W + (size_t)(kbeg + 2 * pk + 1) * N + gnw;

    float acc[2][4][4];
#pragma unroll
    for (int mi = 0; mi < 2; mi++)
#pragma unroll
        for (int ni = 0; ni < 4; ni++)
#pragma unroll
            for (int r = 0; r < 4; r++) acc[mi][ni][r] = 0.f;

    float4 av[4];
    float4 wv0, wv1;

    auto LDG = [&](int t) {
        const float* ap = Ap + t * 32;
#pragma unroll
        for (int r = 0; r < 4; r++)
            av[r] = *reinterpret_cast<const float4*>(ap + (size_t)(32 * r) * K);
        if (wok) {
            wv0 = *reinterpret_cast<const float4*>(Wp0 + (size_t)(t * 32) * N);
            wv1 = *reinterpret_cast<const float4*>(Wp1 + (size_t)(t * 32) * N);
        } else {
            wv0 = make_float4(0.f, 0.f, 0.f, 0.f);
            wv1 = wv0;
        }
    };

    auto STS = [&](int p) {
#pragma unroll
        for (int r = 0; r < 4; r++) {
            int m = sa_r + 32 * r;
            uint2 t2;
            t2.x = packh2(av[r].x, av[r].y);
            t2.y = packh2(av[r].z, av[r].w);
            *reinterpret_cast<uint2*>(&As[p][m][sa_p]) = t2;
        }
        uint4 t4;
        t4.x = packh2(wv0.x, wv1.x);
        t4.y = packh2(wv0.y, wv1.y);
        t4.z = packh2(wv0.z, wv1.z);
        t4.w = packh2(wv0.w, wv1.w);
        *reinterpret_cast<uint4*>(&Ws[p][pk][wc]) = t4;
    };

    LDG(0);
    STS(0);
    __syncthreads();

    int p = 0;
    for (int t = 0; t < kT; t++) {
        if (t + 1 < kT) LDG(t + 1);

#pragma unroll
        for (int ks = 0; ks < 2; ks++) {       // two k=16 steps per 32-k tile
            const int kp = ks * 8;             // k-pair offset
            uint32_t af[2][4];
#pragma unroll
            for (int mi = 0; mi < 2; mi++) {
                int ar = warp_m + mi * 16 + gid;
                af[mi][0] = As[p][ar][kp + tig];
                af[mi][1] = As[p][ar + 8][kp + tig];
                af[mi][2] = As[p][ar][kp + tig + 4];
                af[mi][3] = As[p][ar + 8][kp + tig + 4];
            }
            uint32_t bf[4][2];
#pragma unroll
            for (int ni = 0; ni < 4; ni++) {
                int bc = warp_n + ni * 8 + gid;
                bf[ni][0] = Ws[p][kp + tig][bc];
                bf[ni][1] = Ws[p][kp + tig + 4][bc];
            }
#pragma unroll
            for (int mi = 0; mi < 2; mi++)
#pragma unroll
                for (int ni = 0; ni < 4; ni++) {
                    asm volatile(
                        "mma.sync.aligned.m16n8k16.row.col.f32.f16.f16.f32 "
                        "{%0,%1,%2,%3}, {%4,%5,%6,%7}, {%8,%9}, {%0,%1,%2,%3};\n"
                        : "+f"(acc[mi][ni][0]), "+f"(acc[mi][ni][1]),
                          "+f"(acc[mi][ni][2]), "+f"(acc[mi][ni][3])
                        : "r"(af[mi][0]), "r"(af[mi][1]),
                          "r"(af[mi][2]), "r"(af[mi][3]),
                          "r"(bf[ni][0]), "r"(bf[ni][1]));
                }
        }

        if (t + 1 < kT) STS(p ^ 1);
        __syncthreads();
        p ^= 1;
    }

    // epilogue
#pragma unroll
    for (int mi = 0; mi < 2; mi++) {
        int r0 = bm + warp_m + mi * 16 + gid;
#pragma unroll
        for (int ni = 0; ni < 4; ni++) {
            int c0 = bn + warp_n + ni * 8 + 2 * tig;
            if (c0 < N) {
                float v0 = acc[mi][ni][0], v1 = acc[mi][ni][1];
                float v2 = acc[mi][ni][2], v3 = acc[mi][ni][3];
                if (ADDBIAS) {
                    float bz0 = bias[c0];
                    float bz1 = (c0 + 1 < N) ? bias[c0 + 1] : 0.f;
                    v0 += bz0; v1 += bz1; v2 += bz0; v3 += bz1;
                }
                C[(size_t)r0 * N + c0] = v0;
                C[(size_t)(r0 + 8) * N + c0] = v2;
                if (c0 + 1 < N) {
                    C[(size_t)r0 * N + c0 + 1] = v1;
                    C[(size_t)(r0 + 8) * N + c0 + 1] = v3;
                }
            }
        }
    }
}

// MODE: 0 = plain (full K, bias), 1 = split-K (z = k-chunk, raw partials),
//       2 = dual (z selects arg set, full K, bias)
template <int MODE>
__global__ void __launch_bounds__(256)
gemm_h16p(GemmArgs g0, GemmArgs g1, int M, int N, int K, int kLen) {
    const GemmArgs ga = (MODE == 2 && blockIdx.z == 1) ? g1 : g0;
    const int kbeg = (MODE == 1) ? blockIdx.z * kLen : 0;
    const int kT = ((MODE == 1) ? kLen : K) / 32;
    float* C = ga.C + ((MODE == 1) ? (size_t)blockIdx.z * M * N : 0);
    if (MODE == 1)
        gemm_core<false>(ga.A, ga.W, ga.bias, C, N, K, kbeg, kT);
    else
        gemm_core<true>(ga.A, ga.W, ga.bias, C, N, K, kbeg, kT);
}

// ---------------- exact-fp32 FFMA2 GEMM (attn logits only) ----------------
__global__ void gemm_f32x2_split_kernel(const float* __restrict__ A,
                                        const float* __restrict__ W,
                                        float* __restrict__ C,
                                        int M, int N, int K, int kLen) {
    __shared__ float As[16][128];
    __shared__ float Ws[16][68];

    const int tid = threadIdx.x;
    const int bm = blockIdx.y * 128;
    const int bn = blockIdx.x * 64;
    const int tm = (tid >> 4) * 8;
    const int tn = (tid & 15) * 4;

    const int am = tid >> 1;
    const int ak = (tid & 1) * 8;
    const float* Ap = A + (size_t)(bm + am) * K + ak;
    const int wk = tid >> 4;
    const int wn = (tid & 15) * 4;
    const int gnw = bn + wn;
    const float* Wp = W + (size_t)wk * N + gnw;

    unsigned long long acc[4][4];
#pragma unroll
    for (int i = 0; i < 4; i++)
#pragma unroll
        for (int j = 0; j < 4; j++) acc[i][j] = 0ULL;

    const int kbeg = blockIdx.z * kLen;
    const int kend = kbeg + kLen;

    for (int k0 = kbeg; k0 < kend; k0 += 16) {
        float4 av0 = *reinterpret_cast<const float4*>(Ap + k0);
        float4 av1 = *reinterpret_cast<const float4*>(Ap + k0 + 4);
        float4 wv = make_float4(0.f, 0.f, 0.f, 0.f);
        if (gnw < N)
            wv = *reinterpret_cast<const float4*>(Wp + (size_t)k0 * N);

        __syncthreads();
        As[ak + 0][am] = av0.x; As[ak + 1][am] = av0.y;
        As[ak + 2][am] = av0.z; As[ak + 3][am] = av0.w;
        As[ak + 4][am] = av1.x; As[ak + 5][am] = av1.y;
        As[ak + 6][am] = av1.z; As[ak + 7][am] = av1.w;
        *reinterpret_cast<float4*>(&Ws[wk][wn]) = wv;
        __syncthreads();

#pragma unroll
        for (int k = 0; k < 16; k++) {
            float4 a0 = *reinterpret_cast<const float4*>(&As[k][tm]);
            float4 a1 = *reinterpret_cast<const float4*>(&As[k][tm + 4]);
            float4 w  = *reinterpret_cast<const float4*>(&Ws[k][tn]);
            unsigned long long ap[4], wb[4];
            PACK_F32X2(ap[0], a0.x, a0.y);
            PACK_F32X2(ap[1], a0.z, a0.w);
            PACK_F32X2(ap[2], a1.x, a1.y);
            PACK_F32X2(ap[3], a1.z, a1.w);
            PACK_F32X2(wb[0], w.x, w.x);
            PACK_F32X2(wb[1], w.y, w.y);
            PACK_F32X2(wb[2], w.z, w.z);
            PACK_F32X2(wb[3], w.w, w.w);
#pragma unroll
            for (int i = 0; i < 4; i++)
#pragma unroll
                for (int j = 0; j < 4; j++)
                    FMA_F32X2(acc[i][j], ap[i], wb[j], acc[i][j]);
        }
    }

    float* Cb = C + (size_t)blockIdx.z * M * N;
#pragma unroll
    for (int i = 0; i < 4; i++) {
        int r0 = bm + tm + 2 * i;
#pragma unroll
        for (int j = 0; j < 4; j++) {
            int c = bn + tn + j;
            if (c < N) {
                float lo, hi;
                UNPACK_F32X2(lo, hi, acc[i][j]);
                Cb[(size_t)r0 * N + c] = lo;
                Cb[(size_t)(r0 + 1) * N + c] = hi;
            }
        }
    }
}

// ---------------- softmax (attn) ----------------
__global__ void softmax_attn_kernel(const float* __restrict__ attn_b,
                                    float* __restrict__ out) {
    int b = blockIdx.x;
    int t = threadIdx.x;
    float v = attn_b[t];
#pragma unroll
    for (int s = 0; s < 8; s++)
        v += g_part[(size_t)s * B_ * L_ + b * L_ + t];
    __shared__ float red[256];
    red[t] = v;
    __syncthreads();
    for (int s = 128; s; s >>= 1) {
        if (t < s) red[t] = fmaxf(red[t], red[t + s]);
        __syncthreads();
    }
    float m = red[0];
    __syncthreads();
    float e = expf(v - m);
    red[t] = e;
    __syncthreads();
    for (int s = 128; s; s >>= 1) {
        if (t < s) red[t] += red[t + s];
        __syncthreads();
    }
    out[b * L_ + t] = e / red[0];
}

// ---------------- reduce 2 K-partials + bias + relu -> g_x ----------------
__global__ void reduce_relu_kernel(const float* __restrict__ bias) {
    int i = blockIdx.x * blockDim.x + threadIdx.x;
    int j = i & (H_ - 1);
    float v = g_part[i] + g_part[B_ * H_ + i] + bias[j];
    g_x[i] = fmaxf(v, 0.f);
}

// ---------------- attn_applied -> writes straight into g_comb second half ----------------
__global__ void attn_apply_kernel(const float* __restrict__ attw,
                                  const float* __restrict__ enc) {
    int b = blockIdx.y;
    int hc = blockIdx.x;
    int t = threadIdx.x;
    __shared__ float w[L_];
    w[t] = attw[b * L_ + t];
    __syncthreads();
    int h = hc * 256 + t;
    const float* e = enc + (size_t)b * L_ * H_ + h;
    float acc = 0.f;
#pragma unroll 8
    for (int l = 0; l < L_; l++)
        acc += w[l] * e[(size_t)l * H_];
    // [emb | attn_applied]: emb half already in place from step 1
    g_comb[(size_t)b * H2_ + H_ + h] = acc;
}

// ---------------- GRU elementwise ----------------
__global__ void gru_kernel(const float* __restrict__ h,
                           float* __restrict__ new_h) {
    int i = blockIdx.x * blockDim.x + threadIdx.x;
    int b = i >> 10;
    int j = i & (H_ - 1);
    const float* gib = g_gi + (size_t)b * H3_;
    const float* ghb = g_gh + (size_t)b * H3_;
    float r = 1.f / (1.f + expf(-(gib[j] + ghb[j])));
    float z = 1.f / (1.f + expf(-(gib[H_ + j] + ghb[H_ + j])));
    float n = tanhf(gib[2 * H_ + j] + r * ghb[2 * H_ + j]);
    new_h[i] = (1.f - z) * n + z * h[i];
}

// ---------------- log_softmax (online max+sum, 2 passes total) ----------------
__global__ void logsoftmax_kernel(float* __restrict__ x) {
    int b = blockIdx.x;
    int t = threadIdx.x;
    float* row = x + (size_t)b * V_;
    __shared__ float redm[256];
    __shared__ float reds[256];
    float m = -1e30f, s = 0.f;
    for (int i = t; i < V_; i += 256) {
        float v = row[i];
        float mn = fmaxf(m, v);
        s = s * expf(m - mn) + expf(v - mn);
        m = mn;
    }
    redm[t] = m;
    reds[t] = s;
    __syncthreads();
    for (int st = 128; st; st >>= 1) {
        if (t < st) {
            float m2 = redm[t + st], s2 = reds[t + st];
            float mn = fmaxf(redm[t], m2);
            reds[t] = reds[t] * expf(redm[t] - mn) + s2 * expf(m2 - mn);
            redm[t] = mn;
        }
        __syncthreads();
    }
    float lse = redm[0] + logf(reds[0]);
    for (int i = t; i < V_; i += 256) row[i] -= lse;
}

// ---------------- launch ----------------
extern "C" void kernel_launch(void* const* d_in, const int* in_sizes, int n_in,
                              void* d_out, int out_size) {
    const int*   input_ids = (const int*)d_in[0];
    const float* hidden    = (const float*)d_in[1];
    const float* enc       = (const float*)d_in[2];
    const float* emb       = (const float*)d_in[3];
    const float* attn_w    = (const float*)d_in[4];
    const float* attn_b    = (const float*)d_in[5];
    const float* comb_w    = (const float*)d_in[6];
    const float* comb_b    = (const float*)d_in[7];
    const float* w_ih      = (const float*)d_in[8];
    const float* w_hh      = (const float*)d_in[9];
    const float* b_ih      = (const float*)d_in[10];
    const float* b_hh      = (const float*)d_in[11];
    const float* out_w     = (const float*)d_in[12];
    const float* out_b     = (const float*)d_in[13];

    float* out       = (float*)d_out;
    float* new_h_out = out + (size_t)B_ * V_;
    float* attw_out  = new_h_out + (size_t)B_ * H_;

    float *p_comb, *p_x, *p_gi, *p_gh, *p_part;
    cudaGetSymbolAddress((void**)&p_comb, g_comb);
    cudaGetSymbolAddress((void**)&p_x,    g_x);
    cudaGetSymbolAddress((void**)&p_gi,   g_gi);
    cudaGetSymbolAddress((void**)&p_gh,   g_gh);
    cudaGetSymbolAddress((void**)&p_part, g_part);

    GemmArgs none = {nullptr, nullptr, nullptr, nullptr};

    // 1. g_comb = [emb[ids] | hidden]
    concat_emb_kernel<<<(B_ * H2_) / 256, 256>>>(input_ids, emb, hidden);
    // 2. attn logits, exact fp32, split-K=8 -> partials
    {
        dim3 g(L_ / 64, B_ / 128, 8);
        gemm_f32x2_split_kernel<<<g, 256>>>(p_comb, attn_w, p_part,
                                            B_, L_, H2_, H2_ / 8);
    }
    // 3. reduce + softmax -> attw_out
    softmax_attn_kernel<<<B_, 256>>>(attn_b, attw_out);
    // 4. attn_applied -> g_comb second half (emb half persists from step 1)
    {
        dim3 g(H_ / 256, B_);
        attn_apply_kernel<<<g, 256>>>(attw_out, enc);
    }
    // 5. comb GEMM (fp16 mma), split-K=2 -> partials
    {
        dim3 g(H_ / 64, B_ / 128, 2);
        GemmArgs a0 = {p_comb, comb_w, nullptr, p_part};
        gemm_h16p<1><<<g, 256>>>(a0, none, B_, H_, H2_, H2_ / 2);
    }
    // 6. x = relu(p0 + p1 + bias)
    reduce_relu_kernel<<<(B_ * H_) / 256, 256>>>(comb_b);
    // 7. gi = x@w_ih+b_ih ; gh = hidden@w_hh+b_hh (dual via grid.z)
    {
        dim3 g(H3_ / 64, B_ / 128, 2);
        GemmArgs a0 = {p_x,    w_ih, b_ih, p_gi};
        GemmArgs a1 = {hidden, w_hh, b_hh, p_gh};
        gemm_h16p<2><<<g, 256>>>(a0, a1, B_, H3_, H_, H_);
    }
    // 8. GRU -> new_hidden
    gru_kernel<<<(B_ * H_) / 256, 256>>>(hidden, new_h_out);
    // 9. out-proj (fp16 mma)
    {
        dim3 g((V_ + 63) / 64, B_ / 128, 1);
        GemmArgs a0 = {new_h_out, out_w, out_b, out};
        gemm_h16p<0><<<g, 256>>>(a0, none, B_, V_, H_, H_);
    }
    // 10. log_softmax (online)
    logsoftmax_kernel<<<B_, 256>>>(out);
}

// round 15
// speedup vs baseline: 1.2824x; 1.0289x over previous
#include <cuda_runtime.h>
#include <cuda_bf16.h>
#include <cuda_fp16.h>
#include <math.h>
#include <stdint.h>

// Problem dims
#define B_  512
#define H_  1024
#define L_  256
#define V_  10000
#define H2_ 2048
#define H3_ 3072

// ---------------- scratch (device globals; no allocation) ----------------
__device__ float g_app[B_ * H_];        // attn_applied
__device__ float g_x[B_ * H_];
__device__ float g_gi[B_ * H3_];
__device__ float g_gh[B_ * H3_];
__device__ float g_part[8 * B_ * L_];   // split-K partials (4MB; holds 2*B*H too)

// ---------------- helpers ----------------
__device__ __forceinline__ uint32_t packh2(float lo, float hi) {
    __half2 h = __floats2half2_rn(lo, hi);   // .x = lo (low 16 bits)
    return *reinterpret_cast<uint32_t*>(&h);
}

// ==================== pipelined fp16 mma GEMM (fp32 accum) ====================
// C = A(M,K) @ W(K,N) (+bias). 256 thr = 8 warps (4m x 2n), BM=128 BN=64 BK=32.
// m16n8k16.f16; smem packed half2 (2 k-elems per u32).
// As [2][128][20] u32, Ws [2][16][72] u32 — conflict-free fragment walks.
// A rows optionally gathered through ids (embedding lookup fused into GEMM).
struct GemmArgs {
    const float* A;
    const float* W;
    const float* bias;
    float* C;
};

struct SrcA {
    const float* A;
    const int* ids;   // null -> direct rows
    int lda;
};

template <bool ADDBIAS>
__device__ __forceinline__ void gemm_core(const float* __restrict__ A,
                                          const int* __restrict__ ids,
                                          int lda, int kaoff,
                                          const float* __restrict__ W,
                                          const float* __restrict__ bias,
                                          float* __restrict__ C,
                                          int N, int kbegW, int kT) {
    __shared__ uint32_t As[2][128][20];   // 20480 B
    __shared__ uint32_t Ws[2][16][72];    //  9216 B  (29696 total, static)

    const int tid = threadIdx.x;
    const int lane = tid & 31;
    const int wid = tid >> 5;
    const int gid = lane >> 2;
    const int tig = lane & 3;
    const int warp_m = (wid & 3) * 32;
    const int warp_n = (wid >> 2) * 32;

    const int bm = blockIdx.y * 128;
    const int bn = blockIdx.x * 64;

    // A staging: rows sa_r (+32r), k cols sa_c..sa_c+3 -> 2 u32 pairs
    const int sa_r = tid >> 3;           // 0..31
    const int sa_c = (tid & 7) * 4;      // 0..28
    const int sa_p = sa_c >> 1;          // pair col 0..14
    // W staging: k-pair row pk (covers k=2pk,2pk+1), n cols wc..wc+3
    const int pk = tid >> 4;             // 0..15
    const int wc = (tid & 15) * 4;       // 0..60
    const int gnw = bn + wc;
    const bool wok = (gnw < N);

    // per-stage A row pointers (gather if ids != null)
    const float* Arow[4];
#pragma unroll
    for (int r = 0; r < 4; r++) {
        int row = bm + sa_r + 32 * r;
        size_t src = ids ? (size_t)ids[row] : (size_t)row;
        Arow[r] = A + src * (size_t)lda + kaoff + sa_c;
    }

    const float* Wp0 = W + (size_t)(kbegW + 2 * pk) * N + gnw;
    const float* Wp1 = W + (size_t)(kbegW + 2 * pk + 1) * N + gnw;

    float acc[2][4][4];
#pragma unroll
    for (int mi = 0; mi < 2; mi++)
#pragma unroll
        for (int ni = 0; ni < 4; ni++)
#pragma unroll
            for (int r = 0; r < 4; r++) acc[mi][ni][r] = 0.f;

    float4 av[4];
    float4 wv0, wv1;

    auto LDG = [&](int t) {
#pragma unroll
        for (int r = 0; r < 4; r++)
            av[r] = *reinterpret_cast<const float4*>(Arow[r] + t * 32);
        if (wok) {
            wv0 = *reinterpret_cast<const float4*>(Wp0 + (size_t)(t * 32) * N);
            wv1 = *reinterpret_cast<const float4*>(Wp1 + (size_t)(t * 32) * N);
        } else {
            wv0 = make_float4(0.f, 0.f, 0.f, 0.f);
            wv1 = wv0;
        }
    };

    auto STS = [&](int p) {
#pragma unroll
        for (int r = 0; r < 4; r++) {
            int m = sa_r + 32 * r;
            uint2 t2;
            t2.x = packh2(av[r].x, av[r].y);
            t2.y = packh2(av[r].z, av[r].w);
            *reinterpret_cast<uint2*>(&As[p][m][sa_p]) = t2;
        }
        uint4 t4;
        t4.x = packh2(wv0.x, wv1.x);
        t4.y = packh2(wv0.y, wv1.y);
        t4.z = packh2(wv0.z, wv1.z);
        t4.w = packh2(wv0.w, wv1.w);
        *reinterpret_cast<uint4*>(&Ws[p][pk][wc]) = t4;
    };

    LDG(0);
    STS(0);
    __syncthreads();

    int p = 0;
    for (int t = 0; t < kT; t++) {
        if (t + 1 < kT) LDG(t + 1);

#pragma unroll
        for (int ks = 0; ks < 2; ks++) {       // two k=16 steps per 32-k tile
            const int kp = ks * 8;             // k-pair offset
            uint32_t af[2][4];
#pragma unroll
            for (int mi = 0; mi < 2; mi++) {
                int ar = warp_m + mi * 16 + gid;
                af[mi][0] = As[p][ar][kp + tig];
                af[mi][1] = As[p][ar + 8][kp + tig];
                af[mi][2] = As[p][ar][kp + tig + 4];
                af[mi][3] = As[p][ar + 8][kp + tig + 4];
            }
            uint32_t bf[4][2];
#pragma unroll
            for (int ni = 0; ni < 4; ni++) {
                int bc = warp_n + ni * 8 + gid;
                bf[ni][0] = Ws[p][kp + tig][bc];
                bf[ni][1] = Ws[p][kp + tig + 4][bc];
            }
#pragma unroll
            for (int mi = 0; mi < 2; mi++)
#pragma unroll
                for (int ni = 0; ni < 4; ni++) {
                    asm volatile(
                        "mma.sync.aligned.m16n8k16.row.col.f32.f16.f16.f32 "
                        "{%0,%1,%2,%3}, {%4,%5,%6,%7}, {%8,%9}, {%0,%1,%2,%3};\n"
                        : "+f"(acc[mi][ni][0]), "+f"(acc[mi][ni][1]),
                          "+f"(acc[mi][ni][2]), "+f"(acc[mi][ni][3])
                        : "r"(af[mi][0]), "r"(af[mi][1]),
                          "r"(af[mi][2]), "r"(af[mi][3]),
                          "r"(bf[ni][0]), "r"(bf[ni][1]));
                }
        }

        if (t + 1 < kT) STS(p ^ 1);
        __syncthreads();
        p ^= 1;
    }

    // epilogue
#pragma unroll
    for (int mi = 0; mi < 2; mi++) {
        int r0 = bm + warp_m + mi * 16 + gid;
#pragma unroll
        for (int ni = 0; ni < 4; ni++) {
            int c0 = bn + warp_n + ni * 8 + 2 * tig;
            if (c0 < N) {
                float v0 = acc[mi][ni][0], v1 = acc[mi][ni][1];
                float v2 = acc[mi][ni][2], v3 = acc[mi][ni][3];
                if (ADDBIAS) {
                    float bz0 = bias[c0];
                    float bz1 = (c0 + 1 < N) ? bias[c0 + 1] : 0.f;
                    v0 += bz0; v1 += bz1; v2 += bz0; v3 += bz1;
                }
                C[(size_t)r0 * N + c0] = v0;
                C[(size_t)(r0 + 8) * N + c0] = v2;
                if (c0 + 1 < N) {
                    C[(size_t)r0 * N + c0 + 1] = v1;
                    C[(size_t)(r0 + 8) * N + c0 + 1] = v3;
                }
            }
        }
    }
}

// split-K with two A sources: z < zsplit reads s0 (chunk z), else s1 (chunk z-zsplit).
// Raw partials at Cb + z*M*N, no bias.
__global__ void __launch_bounds__(256)
gemm_h16_split(SrcA s0, SrcA s1, int zsplit, const float* __restrict__ W,
               float* __restrict__ Cb, int M, int N, int kLen) {
    const int z = blockIdx.z;
    const SrcA s = (z < zsplit) ? s0 : s1;
    const int kaoff = ((z < zsplit) ? z : (z - zsplit)) * kLen;
    gemm_core<false>(s.A, s.ids, s.lda, kaoff, W, nullptr,
                     Cb + (size_t)z * M * N, N, z * kLen, kLen / 32);
}

// plain (full K, bias); dual via grid.z when dual != 0
__global__ void __launch_bounds__(256)
gemm_h16(GemmArgs g0, GemmArgs g1, int dual, int N, int K) {
    const GemmArgs ga = (dual && blockIdx.z == 1) ? g1 : g0;
    gemm_core<true>(ga.A, nullptr, K, 0, ga.W, ga.bias, ga.C, N, 0, K / 32);
}

// ---------------- softmax (attn): sum 8 K-partials + bias, then softmax ----------------
__global__ void softmax_attn_kernel(const float* __restrict__ attn_b,
                                    float* __restrict__ out) {
    int b = blockIdx.x;
    int t = threadIdx.x;
    float v = attn_b[t];
#pragma unroll
    for (int s = 0; s < 8; s++)
        v += g_part[(size_t)s * B_ * L_ + b * L_ + t];
    __shared__ float red[256];
    red[t] = v;
    __syncthreads();
    for (int s = 128; s; s >>= 1) {
        if (t < s) red[t] = fmaxf(red[t], red[t + s]);
        __syncthreads();
    }
    float m = red[0];
    __syncthreads();
    float e = expf(v - m);
    red[t] = e;
    __syncthreads();
    for (int s = 128; s; s >>= 1) {
        if (t < s) red[t] += red[t + s];
        __syncthreads();
    }
    out[b * L_ + t] = e / red[0];
}

// ---------------- reduce 2 K-partials + bias + relu -> g_x ----------------
__global__ void reduce_relu_kernel(const float* __restrict__ bias) {
    int i = blockIdx.x * blockDim.x + threadIdx.x;
    int j = i & (H_ - 1);
    float v = g_part[i] + g_part[B_ * H_ + i] + bias[j];
    g_x[i] = fmaxf(v, 0.f);
}

// ---------------- attn_applied -> g_app ----------------
__global__ void attn_apply_kernel(const float* __restrict__ attw,
                                  const float* __restrict__ enc) {
    int b = blockIdx.y;
    int hc = blockIdx.x;
    int t = threadIdx.x;
    __shared__ float w[L_];
    w[t] = attw[b * L_ + t];
    __syncthreads();
    int h = hc * 256 + t;
    const float* e = enc + (size_t)b * L_ * H_ + h;
    float acc = 0.f;
#pragma unroll 8
    for (int l = 0; l < L_; l++)
        acc += w[l] * e[(size_t)l * H_];
    g_app[(size_t)b * H_ + h] = acc;
}

// ---------------- GRU elementwise ----------------
__global__ void gru_kernel(const float* __restrict__ h,
                           float* __restrict__ new_h) {
    int i = blockIdx.x * blockDim.x + threadIdx.x;
    int b = i >> 10;
    int j = i & (H_ - 1);
    const float* gib = g_gi + (size_t)b * H3_;
    const float* ghb = g_gh + (size_t)b * H3_;
    float r = 1.f / (1.f + expf(-(gib[j] + ghb[j])));
    float z = 1.f / (1.f + expf(-(gib[H_ + j] + ghb[H_ + j])));
    float n = tanhf(gib[2 * H_ + j] + r * ghb[2 * H_ + j]);
    new_h[i] = (1.f - z) * n + z * h[i];
}

// ---------------- log_softmax (online max+sum) ----------------
__global__ void logsoftmax_kernel(float* __restrict__ x) {
    int b = blockIdx.x;
    int t = threadIdx.x;
    float* row = x + (size_t)b * V_;
    __shared__ float redm[256];
    __shared__ float reds[256];
    float m = -1e30f, s = 0.f;
    for (int i = t; i < V_; i += 256) {
        float v = row[i];
        float mn = fmaxf(m, v);
        s = s * expf(m - mn) + expf(v - mn);
        m = mn;
    }
    redm[t] = m;
    reds[t] = s;
    __syncthreads();
    for (int st = 128; st; st >>= 1) {
        if (t < st) {
            float m2 = redm[t + st], s2 = reds[t + st];
            float mn = fmaxf(redm[t], m2);
            reds[t] = reds[t] * expf(redm[t] - mn) + s2 * expf(m2 - mn);
            redm[t] = mn;
        }
        __syncthreads();
    }
    float lse = redm[0] + logf(reds[0]);
    for (int i = t; i < V_; i += 256) row[i] -= lse;
}

// ---------------- launch ----------------
extern "C" void kernel_launch(void* const* d_in, const int* in_sizes, int n_in,
                              void* d_out, int out_size) {
    const int*   input_ids = (const int*)d_in[0];
    const float* hidden    = (const float*)d_in[1];
    const float* enc       = (const float*)d_in[2];
    const float* emb       = (const float*)d_in[3];
    const float* attn_w    = (const float*)d_in[4];
    const float* attn_b    = (const float*)d_in[5];
    const float* comb_w    = (const float*)d_in[6];
    const float* comb_b    = (const float*)d_in[7];
    const float* w_ih      = (const float*)d_in[8];
    const float* w_hh      = (const float*)d_in[9];
    const float* b_ih      = (const float*)d_in[10];
    const float* b_hh      = (const float*)d_in[11];
    const float* out_w     = (const float*)d_in[12];
    const float* out_b     = (const float*)d_in[13];

    float* out       = (float*)d_out;
    float* new_h_out = out + (size_t)B_ * V_;
    float* attw_out  = new_h_out + (size_t)B_ * H_;

    float *p_app, *p_x, *p_gi, *p_gh, *p_part;
    cudaGetSymbolAddress((void**)&p_app,  g_app);
    cudaGetSymbolAddress((void**)&p_x,    g_x);
    cudaGetSymbolAddress((void**)&p_gi,   g_gi);
    cudaGetSymbolAddress((void**)&p_gh,   g_gh);
    cudaGetSymbolAddress((void**)&p_part, g_part);

    GemmArgs none = {nullptr, nullptr, nullptr, nullptr};

    SrcA src_emb  = {emb,    input_ids, H_};   // gathered rows
    SrcA src_hid  = {hidden, nullptr,   H_};
    SrcA src_app  = {p_app,  nullptr,   H_};

    // 1. attn logits = [emb[ids] | hidden] @ attn_w, fp16 mma, split-K=8 -> partials
    {
        dim3 g(L_ / 64, B_ / 128, 8);
        gemm_h16_split<<<g, 256>>>(src_emb, src_hid, 4, attn_w, p_part,
                                   B_, L_, H2_ / 8);
    }
    // 2. reduce partials + bias + softmax -> attw_out
    softmax_attn_kernel<<<B_, 256>>>(attn_b, attw_out);
    // 3. attn_applied -> g_app
    {
        dim3 g(H_ / 256, B_);
        attn_apply_kernel<<<g, 256>>>(attw_out, enc);
    }
    // 4. comb GEMM = [emb[ids] | attn_applied] @ comb_w, split-K=2 -> partials
    {
        dim3 g(H_ / 64, B_ / 128, 2);
        gemm_h16_split<<<g, 256>>>(src_emb, src_app, 1, comb_w, p_part,
                                   B_, H_, H2_ / 2);
    }
    // 5. x = relu(p0 + p1 + bias)
    reduce_relu_kernel<<<(B_ * H_) / 256, 256>>>(comb_b);
    // 6. gi = x@w_ih+b_ih ; gh = hidden@w_hh+b_hh (dual via grid.z)
    {
        dim3 g(H3_ / 64, B_ / 128, 2);
        GemmArgs a0 = {p_x,    w_ih, b_ih, p_gi};
        GemmArgs a1 = {hidden, w_hh, b_hh, p_gh};
        gemm_h16<<<g, 256>>>(a0, a1, 1, H3_, H_);
    }
    // 7. GRU -> new_hidden
    gru_kernel<<<(B_ * H_) / 256, 256>>>(hidden, new_h_out);
    // 8. out-proj (fp16 mma)
    {
        dim3 g((V_ + 63) / 64, B_ / 128, 1);
        GemmArgs a0 = {new_h_out, out_w, out_b, out};
        gemm_h16<<<g, 256>>>(a0, none, 0, V_, H_);
    }
    // 9. log_softmax (online)
    logsoftmax_kernel<<<B_, 256>>>(out);
}

// round 16
// speedup vs baseline: 1.3503x; 1.0530x over previous
#include <cuda_runtime.h>
#include <cuda_bf16.h>
#include <cuda_fp16.h>
#include <math.h>
#include <stdint.h>

// Problem dims
#define B_  512
#define H_  1024
#define L_  256
#define V_  10000
#define H2_ 2048
#define H3_ 3072

#define ATTN_S 16   // attn split-K factor
#define COMB_S 4    // comb split-K factor

// ---------------- scratch (device globals; no allocation) ----------------
__device__ float g_app[B_ * H_];        // attn_applied
__device__ float g_x[B_ * H_];
__device__ float g_gi[B_ * H3_];
__device__ float g_gh[B_ * H3_];
__device__ float g_part[ATTN_S * B_ * L_];  // 8MB; also holds COMB_S*B*H

// ---------------- helpers ----------------
__device__ __forceinline__ uint32_t packh2(float lo, float hi) {
    __half2 h = __floats2half2_rn(lo, hi);   // .x = lo (low 16 bits)
    return *reinterpret_cast<uint32_t*>(&h);
}

// ==================== pipelined fp16 mma GEMM (fp32 accum) ====================
// C = A(M,K) @ W(K,N) (+bias). 256 thr = 8 warps (4m x 2n), BM=128 BN=64 BK=32.
// m16n8k16.f16; smem packed half2 (2 k-elems per u32).
// As [2][128][20] u32, Ws [2][16][72] u32 — conflict-free fragment walks.
// A rows optionally gathered through ids (embedding lookup fused into GEMM).
struct GemmArgs {
    const float* A;
    const float* W;
    const float* bias;
    float* C;
};

struct SrcA {
    const float* A;
    const int* ids;   // null -> direct rows
    int lda;
};

template <bool ADDBIAS>
__device__ __forceinline__ void gemm_core(const float* __restrict__ A,
                                          const int* __restrict__ ids,
                                          int lda, int kaoff,
                                          const float* __restrict__ W,
                                          const float* __restrict__ bias,
                                          float* __restrict__ C,
                                          int N, int kbegW, int kT) {
    __shared__ uint32_t As[2][128][20];   // 20480 B
    __shared__ uint32_t Ws[2][16][72];    //  9216 B  (29696 total, static)

    const int tid = threadIdx.x;
    const int lane = tid & 31;
    const int wid = tid >> 5;
    const int gid = lane >> 2;
    const int tig = lane & 3;
    const int warp_m = (wid & 3) * 32;
    const int warp_n = (wid >> 2) * 32;

    const int bm = blockIdx.y * 128;
    const int bn = blockIdx.x * 64;

    // A staging: rows sa_r (+32r), k cols sa_c..sa_c+3 -> 2 u32 pairs
    const int sa_r = tid >> 3;           // 0..31
    const int sa_c = (tid & 7) * 4;      // 0..28
    const int sa_p = sa_c >> 1;          // pair col 0..14
    // W staging: k-pair row pk (covers k=2pk,2pk+1), n cols wc..wc+3
    const int pk = tid >> 4;             // 0..15
    const int wc = (tid & 15) * 4;       // 0..60
    const int gnw = bn + wc;
    const bool wok = (gnw < N);

    // per-stage A row pointers (gather if ids != null)
    const float* Arow[4];
#pragma unroll
    for (int r = 0; r < 4; r++) {
        int row = bm + sa_r + 32 * r;
        size_t src = ids ? (size_t)ids[row] : (size_t)row;
        Arow[r] = A + src * (size_t)lda + kaoff + sa_c;
    }

    const float* Wp0 = W + (size_t)(kbegW + 2 * pk) * N + gnw;
    const float* Wp1 = W + (size_t)(kbegW + 2 * pk + 1) * N + gnw;

    float acc[2][4][4];
#pragma unroll
    for (int mi = 0; mi < 2; mi++)
#pragma unroll
        for (int ni = 0; ni < 4; ni++)
#pragma unroll
            for (int r = 0; r < 4; r++) acc[mi][ni][r] = 0.f;

    float4 av[4];
    float4 wv0, wv1;

    auto LDG = [&](int t) {
#pragma unroll
        for (int r = 0; r < 4; r++)
            av[r] = *reinterpret_cast<const float4*>(Arow[r] + t * 32);
        if (wok) {
            wv0 = *reinterpret_cast<const float4*>(Wp0 + (size_t)(t * 32) * N);
            wv1 = *reinterpret_cast<const float4*>(Wp1 + (size_t)(t * 32) * N);
        } else {
            wv0 = make_float4(0.f, 0.f, 0.f, 0.f);
            wv1 = wv0;
        }
    };

    auto STS = [&](int p) {
#pragma unroll
        for (int r = 0; r < 4; r++) {
            int m = sa_r + 32 * r;
            uint2 t2;
            t2.x = packh2(av[r].x, av[r].y);
            t2.y = packh2(av[r].z, av[r].w);
            *reinterpret_cast<uint2*>(&As[p][m][sa_p]) = t2;
        }
        uint4 t4;
        t4.x = packh2(wv0.x, wv1.x);
        t4.y = packh2(wv0.y, wv1.y);
        t4.z = packh2(wv0.z, wv1.z);
        t4.w = packh2(wv0.w, wv1.w);
        *reinterpret_cast<uint4*>(&Ws[p][pk][wc]) = t4;
    };

    LDG(0);
    STS(0);
    __syncthreads();

    int p = 0;
    for (int t = 0; t < kT; t++) {
        if (t + 1 < kT) LDG(t + 1);

#pragma unroll
        for (int ks = 0; ks < 2; ks++) {       // two k=16 steps per 32-k tile
            const int kp = ks * 8;             // k-pair offset
            uint32_t af[2][4];
#pragma unroll
            for (int mi = 0; mi < 2; mi++) {
                int ar = warp_m + mi * 16 + gid;
                af[mi][0] = As[p][ar][kp + tig];
                af[mi][1] = As[p][ar + 8][kp + tig];
                af[mi][2] = As[p][ar][kp + tig + 4];
                af[mi][3] = As[p][ar + 8][kp + tig + 4];
            }
            uint32_t bf[4][2];
#pragma unroll
            for (int ni = 0; ni < 4; ni++) {
                int bc = warp_n + ni * 8 + gid;
                bf[ni][0] = Ws[p][kp + tig][bc];
                bf[ni][1] = Ws[p][kp + tig + 4][bc];
            }
#pragma unroll
            for (int mi = 0; mi < 2; mi++)
#pragma unroll
                for (int ni = 0; ni < 4; ni++) {
                    asm volatile(
                        "mma.sync.aligned.m16n8k16.row.col.f32.f16.f16.f32 "
                        "{%0,%1,%2,%3}, {%4,%5,%6,%7}, {%8,%9}, {%0,%1,%2,%3};\n"
                        : "+f"(acc[mi][ni][0]), "+f"(acc[mi][ni][1]),
                          "+f"(acc[mi][ni][2]), "+f"(acc[mi][ni][3])
                        : "r"(af[mi][0]), "r"(af[mi][1]),
                          "r"(af[mi][2]), "r"(af[mi][3]),
                          "r"(bf[ni][0]), "r"(bf[ni][1]));
                }
        }

        if (t + 1 < kT) STS(p ^ 1);
        __syncthreads();
        p ^= 1;
    }

    // epilogue
#pragma unroll
    for (int mi = 0; mi < 2; mi++) {
        int r0 = bm + warp_m + mi * 16 + gid;
#pragma unroll
        for (int ni = 0; ni < 4; ni++) {
            int c0 = bn + warp_n + ni * 8 + 2 * tig;
            if (c0 < N) {
                float v0 = acc[mi][ni][0], v1 = acc[mi][ni][1];
                float v2 = acc[mi][ni][2], v3 = acc[mi][ni][3];
                if (ADDBIAS) {
                    float bz0 = bias[c0];
                    float bz1 = (c0 + 1 < N) ? bias[c0 + 1] : 0.f;
                    v0 += bz0; v1 += bz1; v2 += bz0; v3 += bz1;
                }
                C[(size_t)r0 * N + c0] = v0;
                C[(size_t)(r0 + 8) * N + c0] = v2;
                if (c0 + 1 < N) {
                    C[(size_t)r0 * N + c0 + 1] = v1;
                    C[(size_t)(r0 + 8) * N + c0 + 1] = v3;
                }
            }
        }
    }
}

// split-K with two A sources: z < zsplit reads s0 (chunk z), else s1 (chunk z-zsplit).
// Raw partials at Cb + z*M*N, no bias.
__global__ void __launch_bounds__(256)
gemm_h16_split(SrcA s0, SrcA s1, int zsplit, const float* __restrict__ W,
               float* __restrict__ Cb, int M, int N, int kLen) {
    const int z = blockIdx.z;
    const SrcA s = (z < zsplit) ? s0 : s1;
    const int kaoff = ((z < zsplit) ? z : (z - zsplit)) * kLen;
    gemm_core<false>(s.A, s.ids, s.lda, kaoff, W, nullptr,
                     Cb + (size_t)z * M * N, N, z * kLen, kLen / 32);
}

// plain (full K, bias); dual via grid.z when dual != 0
__global__ void __launch_bounds__(256)
gemm_h16(GemmArgs g0, GemmArgs g1, int dual, int N, int K) {
    const GemmArgs ga = (dual && blockIdx.z == 1) ? g1 : g0;
    gemm_core<true>(ga.A, nullptr, K, 0, ga.W, ga.bias, ga.C, N, 0, K / 32);
}

// ---------------- softmax (attn): sum ATTN_S K-partials + bias, then softmax ----------------
__global__ void softmax_attn_kernel(const float* __restrict__ attn_b,
                                    float* __restrict__ out) {
    int b = blockIdx.x;
    int t = threadIdx.x;
    float v = attn_b[t];
#pragma unroll
    for (int s = 0; s < ATTN_S; s++)
        v += g_part[(size_t)s * B_ * L_ + b * L_ + t];
    __shared__ float red[256];
    red[t] = v;
    __syncthreads();
    for (int s = 128; s; s >>= 1) {
        if (t < s) red[t] = fmaxf(red[t], red[t + s]);
        __syncthreads();
    }
    float m = red[0];
    __syncthreads();
    float e = expf(v - m);
    red[t] = e;
    __syncthreads();
    for (int s = 128; s; s >>= 1) {
        if (t < s) red[t] += red[t + s];
        __syncthreads();
    }
    out[b * L_ + t] = e / red[0];
}

// ---------------- reduce COMB_S K-partials + bias + relu -> g_x ----------------
__global__ void reduce_relu_kernel(const float* __restrict__ bias) {
    int i = blockIdx.x * blockDim.x + threadIdx.x;
    int j = i & (H_ - 1);
    float v = bias[j];
#pragma unroll
    for (int s = 0; s < COMB_S; s++)
        v += g_part[(size_t)s * B_ * H_ + i];
    g_x[i] = fmaxf(v, 0.f);
}

// ---------------- attn_applied -> g_app ----------------
__global__ void attn_apply_kernel(const float* __restrict__ attw,
                                  const float* __restrict__ enc) {
    int b = blockIdx.y;
    int hc = blockIdx.x;
    int t = threadIdx.x;
    __shared__ float w[L_];
    w[t] = attw[b * L_ + t];
    __syncthreads();
    int h = hc * 256 + t;
    const float* e = enc + (size_t)b * L_ * H_ + h;
    float acc = 0.f;
#pragma unroll 8
    for (int l = 0; l < L_; l++)
        acc += w[l] * e[(size_t)l * H_];
    g_app[(size_t)b * H_ + h] = acc;
}

// ---------------- GRU elementwise ----------------
__global__ void gru_kernel(const float* __restrict__ h,
                           float* __restrict__ new_h) {
    int i = blockIdx.x * blockDim.x + threadIdx.x;
    int b = i >> 10;
    int j = i & (H_ - 1);
    const float* gib = g_gi + (size_t)b * H3_;
    const float* ghb = g_gh + (size_t)b * H3_;
    float r = 1.f / (1.f + expf(-(gib[j] + ghb[j])));
    float z = 1.f / (1.f + expf(-(gib[H_ + j] + ghb[H_ + j])));
    float n = tanhf(gib[2 * H_ + j] + r * ghb[2 * H_ + j]);
    new_h[i] = (1.f - z) * n + z * h[i];
}

// ---------------- log_softmax (online max+sum) ----------------
__global__ void logsoftmax_kernel(float* __restrict__ x) {
    int b = blockIdx.x;
    int t = threadIdx.x;
    float* row = x + (size_t)b * V_;
    __shared__ float redm[256];
    __shared__ float reds[256];
    float m = -1e30f, s = 0.f;
    for (int i = t; i < V_; i += 256) {
        float v = row[i];
        float mn = fmaxf(m, v);
        s = s * expf(m - mn) + expf(v - mn);
        m = mn;
    }
    redm[t] = m;
    reds[t] = s;
    __syncthreads();
    for (int st = 128; st; st >>= 1) {
        if (t < st) {
            float m2 = redm[t + st], s2 = reds[t + st];
            float mn = fmaxf(redm[t], m2);
            reds[t] = reds[t] * expf(redm[t] - mn) + s2 * expf(m2 - mn);
            redm[t] = mn;
        }
        __syncthreads();
    }
    float lse = redm[0] + logf(reds[0]);
    for (int i = t; i < V_; i += 256) row[i] -= lse;
}

// ---------------- launch ----------------
extern "C" void kernel_launch(void* const* d_in, const int* in_sizes, int n_in,
                              void* d_out, int out_size) {
    const int*   input_ids = (const int*)d_in[0];
    const float* hidden    = (const float*)d_in[1];
    const float* enc       = (const float*)d_in[2];
    const float* emb       = (const float*)d_in[3];
    const float* attn_w    = (const float*)d_in[4];
    const float* attn_b    = (const float*)d_in[5];
    const float* comb_w    = (const float*)d_in[6];
    const float* comb_b    = (const float*)d_in[7];
    const float* w_ih      = (const float*)d_in[8];
    const float* w_hh      = (const float*)d_in[9];
    const float* b_ih      = (const float*)d_in[10];
    const float* b_hh      = (const float*)d_in[11];
    const float* out_w     = (const float*)d_in[12];
    const float* out_b     = (const float*)d_in[13];

    float* out       = (float*)d_out;
    float* new_h_out = out + (size_t)B_ * V_;
    float* attw_out  = new_h_out + (size_t)B_ * H_;

    float *p_app, *p_x, *p_gi, *p_gh, *p_part;
    cudaGetSymbolAddress((void**)&p_app,  g_app);
    cudaGetSymbolAddress((void**)&p_x,    g_x);
    cudaGetSymbolAddress((void**)&p_gi,   g_gi);
    cudaGetSymbolAddress((void**)&p_gh,   g_gh);
    cudaGetSymbolAddress((void**)&p_part, g_part);

    GemmArgs none = {nullptr, nullptr, nullptr, nullptr};

    SrcA src_emb  = {emb,    input_ids, H_};   // gathered rows
    SrcA src_hid  = {hidden, nullptr,   H_};
    SrcA src_app  = {p_app,  nullptr,   H_};

    // 1. attn logits = [emb[ids] | hidden] @ attn_w, fp16 mma, split-K=16 -> partials
    {
        dim3 g(L_ / 64, B_ / 128, ATTN_S);
        gemm_h16_split<<<g, 256>>>(src_emb, src_hid, ATTN_S / 2, attn_w, p_part,
                                   B_, L_, H2_ / ATTN_S);
    }
    // 2. reduce partials + bias + softmax -> attw_out
    softmax_attn_kernel<<<B_, 256>>>(attn_b, attw_out);
    // 3. attn_applied -> g_app
    {
        dim3 g(H_ / 256, B_);
        attn_apply_kernel<<<g, 256>>>(attw_out, enc);
    }
    // 4. comb GEMM = [emb[ids] | attn_applied] @ comb_w, split-K=4 -> partials
    {
        dim3 g(H_ / 64, B_ / 128, COMB_S);
        gemm_h16_split<<<g, 256>>>(src_emb, src_app, COMB_S / 2, comb_w, p_part,
                                   B_, H_, H2_ / COMB_S);
    }
    // 5. x = relu(sum partials + bias)
    reduce_relu_kernel<<<(B_ * H_) / 256, 256>>>(comb_b);
    // 6. gi = x@w_ih+b_ih ; gh = hidden@w_hh+b_hh (dual via grid.z)
    {
        dim3 g(H3_ / 64, B_ / 128, 2);
        GemmArgs a0 = {p_x,    w_ih, b_ih, p_gi};
        GemmArgs a1 = {hidden, w_hh, b_hh, p_gh};
        gemm_h16<<<g, 256>>>(a0, a1, 1, H3_, H_);
    }
    // 7. GRU -> new_hidden
    gru_kernel<<<(B_ * H_) / 256, 256>>>(hidden, new_h_out);
    // 8. out-proj (fp16 mma)
    {
        dim3 g((V_ + 63) / 64, B_ / 128, 1);
        GemmArgs a0 = {new_h_out, out_w, out_b, out};
        gemm_h16<<<g, 256>>>(a0, none, 0, V_, H_);
    }
    // 9. log_softmax (online)
    logsoftmax_kernel<<<B_, 256>>>(out);
}